// round 7
// baseline (speedup 1.0000x reference)
#include <cuda_runtime.h>
#include <cuda_bf16.h>
#include <cstdint>
#include <math.h>

// Problem constants
#define N_TOK 2048      // B*T
#define HDIM  768
#define NEXP  16
#define TOPK  4
#define I2    3072      // 2*I
#define IDIM  1536      // I
#define NSLOT (N_TOK*TOPK)

// GEMM pipeline config
#define KSTG  64                      // k per stage (64 bf16 = 128B rows)
#define NBUF  3
#define STGBYTES 32768                // A 16KB + B 16KB (both bf16)
#define SMEM_BYTES (NBUF*STGBYTES)    // 98304

// ---------------- scratch (static __device__, no allocs) ----------------
__device__ __align__(16) __nv_bfloat16 g_t[N_TOK*HDIM];
__device__ __align__(16) __nv_bfloat16 g_a[(size_t)NSLOT*IDIM];
__device__ float g_y[(size_t)NSLOT*HDIM];
__device__ int   g_topk_idx[NSLOT];
__device__ float g_topk_w[NSLOT];
__device__ int   g_cnt[NEXP];
__device__ int   g_off[NEXP];
__device__ int   g_perm[NSLOT];
__device__ int   g_slot[NSLOT];

// ---------------- asm helpers ----------------
__device__ __forceinline__ uint32_t smem_u32(const void* p) {
    uint32_t a;
    asm("{ .reg .u64 t; cvta.to.shared.u64 t, %1; cvt.u32.u64 %0, t; }" : "=r"(a) : "l"(p));
    return a;
}
__device__ __forceinline__ uint32_t packbf2(float lo, float hi) {
    __nv_bfloat162 t = __floats2bfloat162_rn(lo, hi);
    return *reinterpret_cast<uint32_t*>(&t);
}
#define CPASYNC16(dst, src) \
    asm volatile("cp.async.cg.shared.global [%0], [%1], 16;" :: "r"(dst), "l"(src) : "memory")
#define CPCOMMIT() asm volatile("cp.async.commit_group;" ::: "memory")
#define CPWAIT1()  asm volatile("cp.async.wait_group 1;" ::: "memory")
#define LDSM4(r0, r1, r2, r3, addr) \
    asm volatile("ldmatrix.sync.aligned.m8n8.x4.shared.b16 {%0,%1,%2,%3}, [%4];" \
        : "=r"(r0), "=r"(r1), "=r"(r2), "=r"(r3) : "r"(addr))

__device__ __forceinline__ void mma_bf16(float* d, const uint32_t* a, const uint32_t* b) {
    asm volatile(
        "mma.sync.aligned.m16n8k16.row.col.f32.bf16.bf16.f32 "
        "{%0,%1,%2,%3},{%4,%5,%6,%7},{%8,%9},{%0,%1,%2,%3};"
        : "+f"(d[0]), "+f"(d[1]), "+f"(d[2]), "+f"(d[3])
        : "r"(a[0]), "r"(a[1]), "r"(a[2]), "r"(a[3]),
          "r"(b[0]), "r"(b[1]));
}

// ---------------- kernel 1: router (no count atomics) ----------------
__global__ __launch_bounds__(256) void router_k(
    const float* __restrict__ x, const float* __restrict__ nscale,
    const float* __restrict__ gw, const float* __restrict__ gb)
{
    int n = blockIdx.x;
    int tid = threadIdx.x, warp = tid >> 5, lane = tid & 31;
    const float* xp = x + (size_t)n * HDIM;

    float v[3];
    float ss = 0.f;
#pragma unroll
    for (int i = 0; i < 3; i++) { v[i] = xp[tid + i*256]; ss += v[i]*v[i]; }
#pragma unroll
    for (int o = 16; o; o >>= 1) ss += __shfl_xor_sync(0xffffffffu, ss, o);

    __shared__ float sred[8];
    __shared__ float sg[8][16];
    __shared__ float logits[16];
    if (lane == 0) sred[warp] = ss;
    __syncthreads();
    float tot = 0.f;
#pragma unroll
    for (int w = 0; w < 8; w++) tot += sred[w];
    float inv = rsqrtf(tot * (1.0f/HDIM) + 1e-5f);

    float t[3];
#pragma unroll
    for (int i = 0; i < 3; i++) {
        int h = tid + i*256;
        t[i] = v[i] * inv * nscale[h];
        g_t[(size_t)n*HDIM + h] = __float2bfloat16(t[i]);
    }

    float p[16];
#pragma unroll
    for (int e = 0; e < 16; e++) p[e] = 0.f;
#pragma unroll
    for (int i = 0; i < 3; i++) {
        int h = tid + i*256;
#pragma unroll
        for (int e = 0; e < 16; e++) p[e] += t[i] * gw[e*HDIM + h];
    }
#pragma unroll
    for (int e = 0; e < 16; e++)
#pragma unroll
        for (int o = 16; o; o >>= 1) p[e] += __shfl_xor_sync(0xffffffffu, p[e], o);
    if (lane == 0) {
#pragma unroll
        for (int e = 0; e < 16; e++) sg[warp][e] = p[e];
    }
    __syncthreads();
    if (tid < 16) {
        float s = gb[tid];
#pragma unroll
        for (int w = 0; w < 8; w++) s += sg[w][tid];
        logits[tid] = s;
    }
    __syncthreads();

    if (tid == 0) {
        float vals[TOPK]; int idx[TOPK];
        bool used[16];
#pragma unroll
        for (int e = 0; e < 16; e++) used[e] = false;
        for (int k = 0; k < TOPK; k++) {
            float best = -1e30f; int bi = 0;
            for (int e = 0; e < 16; e++)
                if (!used[e] && logits[e] > best) { best = logits[e]; bi = e; }
            used[bi] = true; vals[k] = best; idx[k] = bi;
        }
        float m = vals[0], s = 0.f, w4[TOPK];
        for (int k = 0; k < TOPK; k++) { w4[k] = expf(vals[k] - m); s += w4[k]; }
        float rs = 1.f / s;
        for (int k = 0; k < TOPK; k++) {
            g_topk_idx[n*TOPK + k] = idx[k];
            g_topk_w[n*TOPK + k]   = w4[k] * rs;
        }
    }
}

// ---------------- kernel 2: fused histogram + scan + scatter (1 CTA) ----------------
__global__ __launch_bounds__(1024) void sortscan_k() {
    __shared__ int scnt[NEXP];
    __shared__ int soff[NEXP];
    __shared__ int scur[NEXP];
    int tid = threadIdx.x;
    if (tid < NEXP) scnt[tid] = 0;
    __syncthreads();
#pragma unroll
    for (int i = 0; i < NSLOT/1024; i++)
        atomicAdd(&scnt[g_topk_idx[tid + i*1024]], 1);
    __syncthreads();
    if (tid == 0) {
        int run = 0;
        for (int e = 0; e < NEXP; e++) {
            soff[e] = run; scur[e] = run; run += scnt[e];
        }
    }
    __syncthreads();
    if (tid < NEXP) { g_cnt[tid] = scnt[tid]; g_off[tid] = soff[tid]; }
#pragma unroll
    for (int i = 0; i < NSLOT/1024; i++) {
        int idx = tid + i*1024;
        int e = g_topk_idx[idx];
        int pos = atomicAdd(&scur[e], 1);
        g_perm[pos] = idx >> 2;      // token
        g_slot[idx] = pos;
    }
}

// ================= GEMM core =================
// Tile: 128(m) x 128(n), k-stage 64 bf16. 256 thr. warp_m=(w&3)*32, warp_n=(w>>2)*64.
// A (bf16 activations) via cp.async; B (fp32 weights) via LDG + cvt + STS, reg-prefetched.

struct FragAcc { float a[2][8][4]; };

__device__ __forceinline__ void gemm_compute_stage(
    uint32_t Ab, uint32_t Bb, int lane, int warp_m, int warp_n, FragAcc& acc)
{
    int g = lane >> 3, r8 = lane & 7;
#pragma unroll
    for (int kk = 0; kk < 4; kk++) {
        int cb = kk * 2;
        uint32_t af[2][4], bf[8][2];
#pragma unroll
        for (int im = 0; im < 2; im++) {
            int row = warp_m + im*16 + (g & 1)*8 + r8;
            int ch  = cb + (g >> 1);
            uint32_t addr = Ab + row*128 + ((ch ^ (row & 7)) * 16);
            LDSM4(af[im][0], af[im][1], af[im][2], af[im][3], addr);
        }
#pragma unroll
        for (int p = 0; p < 4; p++) {
            int row = warp_n + p*16 + (g >> 1)*8 + r8;
            int ch  = cb + (g & 1);
            uint32_t addr = Bb + row*128 + ((ch ^ (row & 7)) * 16);
            LDSM4(bf[2*p][0], bf[2*p][1], bf[2*p+1][0], bf[2*p+1][1], addr);
        }
#pragma unroll
        for (int im = 0; im < 2; im++)
#pragma unroll
            for (int jn = 0; jn < 8; jn++)
                mma_bf16(acc.a[im][jn], af[im], bf[jn]);
    }
}

// A prefetch: 4x cp.async 16B per thread (2 thr/row, 64B halves)
__device__ __forceinline__ void prefetch_A(
    uint32_t sb, int s, int kt, const __nv_bfloat16* arow, int lrow, int lc0)
{
    uint32_t Ab = sb + (uint32_t)(s % NBUF) * STGBYTES;
    int xr = lrow & 7;
#pragma unroll
    for (int c = 0; c < 4; c++) {
        int cc = lc0 + c;
        CPASYNC16(Ab + lrow*128 + ((cc ^ xr) * 16), arow + kt + cc*8);
    }
}

// B global fetch (fp32): 8x float4 per thread = 32 floats
__device__ __forceinline__ void fetch_B(float4* pb, const float* brow, int kt, int lc0f) {
    const float4* src = reinterpret_cast<const float4*>(brow + kt + lc0f*8);
#pragma unroll
    for (int q = 0; q < 8; q++) pb[q] = src[q];
}
// B store: convert 32 fp32 -> 16 bf16x2 -> 4x STS.128 into swizzled chunks
__device__ __forceinline__ void store_B(
    uint32_t sb, int s, const float4* pb, int lrow, int lc0)
{
    uint32_t Bb = sb + (uint32_t)(s % NBUF) * STGBYTES + 16384;
    int xr = lrow & 7;
#pragma unroll
    for (int c = 0; c < 4; c++) {
        int cc = lc0 + c;
        float4 u = pb[2*c], v = pb[2*c+1];
        asm volatile("st.shared.v4.b32 [%0], {%1,%2,%3,%4};"
            :: "r"(Bb + lrow*128 + ((cc ^ xr) * 16)),
               "r"(packbf2(u.x, u.y)), "r"(packbf2(u.z, u.w)),
               "r"(packbf2(v.x, v.y)), "r"(packbf2(v.z, v.w)) : "memory");
    }
}

// ---------------- kernel 3: grouped GEMM1 + swiglu ----------------
__global__ __launch_bounds__(256, 1) void gemm1_k(
    const float* __restrict__ w1, const float* __restrict__ b1)
{
    int e  = blockIdx.z;
    int Me = g_cnt[e];
    int m0 = blockIdx.x * 128;
    if (m0 >= Me) return;
    int n0  = blockIdx.y * 128;
    int off = g_off[e];

    extern __shared__ char smem[];
    uint32_t sb = smem_u32(smem);
    int tid = threadIdx.x, warp = tid >> 5, lane = tid & 31;
    int warp_m = (warp & 3) * 32, warp_n = (warp >> 2) * 64;

    int lrow = tid >> 1;
    int lc0  = (tid & 1) * 4;
    int am = m0 + lrow;
    int tok = (am < Me) ? g_perm[off + am] : g_perm[off];
    const __nv_bfloat16* arow = g_t + (size_t)tok * HDIM;
    const float* brow = w1 + (size_t)e * I2 * HDIM + (size_t)(n0 + lrow) * HDIM;

    FragAcc acc;
#pragma unroll
    for (int a = 0; a < 2; a++)
#pragma unroll
        for (int b = 0; b < 8; b++)
#pragma unroll
            for (int c = 0; c < 4; c++) acc.a[a][b][c] = 0.f;

    const int NS = HDIM / KSTG;  // 12
    float4 pb[8];
    fetch_B(pb, brow, 0, lc0);
    prefetch_A(sb, 0, 0, arow, lrow, lc0); CPCOMMIT();
    prefetch_A(sb, 1, KSTG, arow, lrow, lc0); CPCOMMIT();

    for (int s = 0; s < NS; s++) {
        CPWAIT1();
        __syncthreads();              // A(s) visible; all compute(s-1) done
        store_B(sb, s, pb, lrow, lc0);
        if (s + 2 < NS) prefetch_A(sb, s + 2, (s + 2) * KSTG, arow, lrow, lc0);
        CPCOMMIT();
        if (s + 1 < NS) fetch_B(pb, brow, (s + 1) * KSTG, lc0);
        __syncthreads();              // B(s) visible
        uint32_t Ab = sb + (uint32_t)(s % NBUF) * STGBYTES;
        gemm_compute_stage(Ab, Ab + 16384, lane, warp_m, warp_n, acc);
    }

    // epilogue: bias + swiglu -> bf16 g_a
    const float* B1 = b1 + (size_t)e * I2 + n0;
#pragma unroll
    for (int im = 0; im < 2; im++) {
        int gr = lane >> 2, tg = lane & 3;
        int ml = warp_m + im*16 + gr;
#pragma unroll
        for (int jn = 0; jn < 8; jn++) {
            int nl = warp_n + jn*8 + tg*2;
            float be = B1[nl], bo = B1[nl + 1];
#pragma unroll
            for (int rr = 0; rr < 2; rr++) {
                int r = ml + rr*8;
                if (m0 + r < Me) {
                    float hg = acc.a[im][jn][rr*2+0] + be;
                    float hl = acc.a[im][jn][rr*2+1] + bo;
                    hg = fminf(hg, 7.f);
                    hl = fminf(fmaxf(hl, -7.f), 7.f);
                    float av = hg / (1.f + expf(-1.702f * hg)) * (hl + 1.f);
                    g_a[(size_t)(off + m0 + r)*IDIM + ((n0 + nl) >> 1)] = __float2bfloat16(av);
                }
            }
        }
    }
}

// ---------------- kernel 4: grouped GEMM2 ----------------
__global__ __launch_bounds__(256, 1) void gemm2_k(
    const float* __restrict__ w2, const float* __restrict__ b2)
{
    int e  = blockIdx.z;
    int Me = g_cnt[e];
    int m0 = blockIdx.x * 128;
    if (m0 >= Me) return;
    int n0  = blockIdx.y * 128;
    int off = g_off[e];

    extern __shared__ char smem[];
    uint32_t sb = smem_u32(smem);
    int tid = threadIdx.x, warp = tid >> 5, lane = tid & 31;
    int warp_m = (warp & 3) * 32, warp_n = (warp >> 2) * 64;

    int lrow = tid >> 1;
    int lc0  = (tid & 1) * 4;
    int arowi = (m0 + lrow < Me) ? (m0 + lrow) : 0;
    const __nv_bfloat16* arow = g_a + (size_t)(off + arowi) * IDIM;
    const float* brow = w2 + (size_t)e * HDIM * IDIM + (size_t)(n0 + lrow) * IDIM;

    FragAcc acc;
#pragma unroll
    for (int a = 0; a < 2; a++)
#pragma unroll
        for (int b = 0; b < 8; b++)
#pragma unroll
            for (int c = 0; c < 4; c++) acc.a[a][b][c] = 0.f;

    const int NS = IDIM / KSTG;  // 24
    float4 pb[8];
    fetch_B(pb, brow, 0, lc0);
    prefetch_A(sb, 0, 0, arow, lrow, lc0); CPCOMMIT();
    prefetch_A(sb, 1, KSTG, arow, lrow, lc0); CPCOMMIT();

    for (int s = 0; s < NS; s++) {
        CPWAIT1();
        __syncthreads();
        store_B(sb, s, pb, lrow, lc0);
        if (s + 2 < NS) prefetch_A(sb, s + 2, (s + 2) * KSTG, arow, lrow, lc0);
        CPCOMMIT();
        if (s + 1 < NS) fetch_B(pb, brow, (s + 1) * KSTG, lc0);
        __syncthreads();
        uint32_t Ab = sb + (uint32_t)(s % NBUF) * STGBYTES;
        gemm_compute_stage(Ab, Ab + 16384, lane, warp_m, warp_n, acc);
    }

    const float* B2 = b2 + (size_t)e * HDIM + n0;
#pragma unroll
    for (int im = 0; im < 2; im++) {
        int gr = lane >> 2, tg = lane & 3;
        int ml = warp_m + im*16 + gr;
#pragma unroll
        for (int jn = 0; jn < 8; jn++) {
            int nl = warp_n + jn*8 + tg*2;
            float be = B2[nl], bo = B2[nl + 1];
#pragma unroll
            for (int rr = 0; rr < 2; rr++) {
                int r = ml + rr*8;
                if (m0 + r < Me) {
                    float2 v = make_float2(acc.a[im][jn][rr*2+0] + be,
                                           acc.a[im][jn][rr*2+1] + bo);
                    *reinterpret_cast<float2*>(
                        g_y + (size_t)(off + m0 + r)*HDIM + n0 + nl) = v;
                }
            }
        }
    }
}

// ---------------- kernel 5: combine ----------------
__global__ __launch_bounds__(256) void combine_k(
    const float* __restrict__ x, float* __restrict__ out)
{
    int n = blockIdx.x, tid = threadIdx.x;
    int s[TOPK]; float w[TOPK];
#pragma unroll
    for (int k = 0; k < TOPK; k++) {
        s[k] = g_slot[n*TOPK + k];
        w[k] = g_topk_w[n*TOPK + k];
    }
#pragma unroll
    for (int i = 0; i < 3; i++) {
        int h = tid + i*256;
        float acc = x[(size_t)n*HDIM + h];
#pragma unroll
        for (int k = 0; k < TOPK; k++)
            acc += w[k] * g_y[(size_t)s[k]*HDIM + h];
        out[(size_t)n*HDIM + h] = acc;
    }
}

// ---------------- launch ----------------
extern "C" void kernel_launch(void* const* d_in, const int* in_sizes, int n_in,
                              void* d_out, int out_size)
{
    const float* x      = (const float*)d_in[0];
    const float* nscale = (const float*)d_in[1];
    const float* gw     = (const float*)d_in[2];
    const float* gb     = (const float*)d_in[3];
    const float* w1     = (const float*)d_in[4];
    const float* b1     = (const float*)d_in[5];
    const float* w2     = (const float*)d_in[6];
    const float* b2     = (const float*)d_in[7];
    float* out = (float*)d_out;

    cudaFuncSetAttribute(gemm1_k, cudaFuncAttributeMaxDynamicSharedMemorySize, SMEM_BYTES);
    cudaFuncSetAttribute(gemm2_k, cudaFuncAttributeMaxDynamicSharedMemorySize, SMEM_BYTES);

    router_k<<<N_TOK, 256>>>(x, nscale, gw, gb);               // launch 0
    sortscan_k<<<1, 1024>>>();                                 // launch 1
    gemm1_k<<<dim3(16, I2/128, NEXP), 256, SMEM_BYTES>>>(w1, b1);   // launch 2
    gemm2_k<<<dim3(16, HDIM/128, NEXP), 256, SMEM_BYTES>>>(w2, b2); // launch 3 (ncu target)
    combine_k<<<N_TOK, 256>>>(x, out);                         // launch 4
}

// round 8
// speedup vs baseline: 1.6347x; 1.6347x over previous
#include <cuda_runtime.h>
#include <cuda_bf16.h>
#include <cstdint>
#include <math.h>

// Problem constants
#define N_TOK 2048      // B*T
#define HDIM  768
#define NEXP  16
#define TOPK  4
#define I2    3072      // 2*I
#define IDIM  1536      // I
#define NSLOT (N_TOK*TOPK)
#define W1ELEMS (NEXP*I2*HDIM)
#define W2ELEMS (NEXP*HDIM*IDIM)

// GEMM pipeline config
#define KSTG  64                      // k per stage (64 bf16 = 128B rows)
#define NBUF  3
#define STGBYTES 32768                // A 16KB + B 16KB (both bf16)
#define SMEM_BYTES (NBUF*STGBYTES)    // 98304

// ---------------- scratch (static __device__, no allocs) ----------------
__device__ __align__(16) __nv_bfloat16 g_t[N_TOK*HDIM];
__device__ __align__(16) __nv_bfloat16 g_w1b[W1ELEMS];
__device__ __align__(16) __nv_bfloat16 g_w2b[W2ELEMS];
__device__ __align__(16) __nv_bfloat16 g_a[(size_t)NSLOT*IDIM];
__device__ float g_y[(size_t)NSLOT*HDIM];
__device__ int   g_topk_idx[NSLOT];
__device__ float g_topk_w[NSLOT];
__device__ int   g_cnt[NEXP];
__device__ int   g_off[NEXP];
__device__ int   g_perm[NSLOT];
__device__ int   g_slot[NSLOT];

// ---------------- asm helpers ----------------
__device__ __forceinline__ uint32_t smem_u32(const void* p) {
    uint32_t a;
    asm("{ .reg .u64 t; cvta.to.shared.u64 t, %1; cvt.u32.u64 %0, t; }" : "=r"(a) : "l"(p));
    return a;
}
__device__ __forceinline__ uint32_t packbf2(float lo, float hi) {
    __nv_bfloat162 t = __floats2bfloat162_rn(lo, hi);
    return *reinterpret_cast<uint32_t*>(&t);
}
#define CPASYNC16(dst, src) \
    asm volatile("cp.async.cg.shared.global [%0], [%1], 16;" :: "r"(dst), "l"(src) : "memory")
#define CPCOMMIT() asm volatile("cp.async.commit_group;" ::: "memory")
#define CPWAIT1()  asm volatile("cp.async.wait_group 1;" ::: "memory")
#define LDSM4(r0, r1, r2, r3, addr) \
    asm volatile("ldmatrix.sync.aligned.m8n8.x4.shared.b16 {%0,%1,%2,%3}, [%4];" \
        : "=r"(r0), "=r"(r1), "=r"(r2), "=r"(r3) : "r"(addr))

__device__ __forceinline__ void mma_bf16(float* d, const uint32_t* a, const uint32_t* b) {
    asm volatile(
        "mma.sync.aligned.m16n8k16.row.col.f32.bf16.bf16.f32 "
        "{%0,%1,%2,%3},{%4,%5,%6,%7},{%8,%9},{%0,%1,%2,%3};"
        : "+f"(d[0]), "+f"(d[1]), "+f"(d[2]), "+f"(d[3])
        : "r"(a[0]), "r"(a[1]), "r"(a[2]), "r"(a[3]),
          "r"(b[0]), "r"(b[1]));
}

// ---------------- kernel 0: weight fp32 -> bf16 ----------------
__global__ __launch_bounds__(256) void convw_k(
    const float4* __restrict__ w1, const float4* __restrict__ w2)
{
    int i = blockIdx.x * blockDim.x + threadIdx.x;
    const int n1 = W1ELEMS / 4, n2 = W2ELEMS / 4;
    if (i < n1) {
        float4 v = w1[i];
        reinterpret_cast<uint2*>(g_w1b)[i] = make_uint2(packbf2(v.x, v.y), packbf2(v.z, v.w));
    } else {
        i -= n1;
        if (i < n2) {
            float4 v = w2[i];
            reinterpret_cast<uint2*>(g_w2b)[i] = make_uint2(packbf2(v.x, v.y), packbf2(v.z, v.w));
        }
    }
}

// ---------------- kernel 1: router (no count atomics) ----------------
__global__ __launch_bounds__(256) void router_k(
    const float* __restrict__ x, const float* __restrict__ nscale,
    const float* __restrict__ gw, const float* __restrict__ gb)
{
    int n = blockIdx.x;
    int tid = threadIdx.x, warp = tid >> 5, lane = tid & 31;
    const float* xp = x + (size_t)n * HDIM;

    float v[3];
    float ss = 0.f;
#pragma unroll
    for (int i = 0; i < 3; i++) { v[i] = xp[tid + i*256]; ss += v[i]*v[i]; }
#pragma unroll
    for (int o = 16; o; o >>= 1) ss += __shfl_xor_sync(0xffffffffu, ss, o);

    __shared__ float sred[8];
    __shared__ float sg[8][16];
    __shared__ float logits[16];
    if (lane == 0) sred[warp] = ss;
    __syncthreads();
    float tot = 0.f;
#pragma unroll
    for (int w = 0; w < 8; w++) tot += sred[w];
    float inv = rsqrtf(tot * (1.0f/HDIM) + 1e-5f);

    float t[3];
#pragma unroll
    for (int i = 0; i < 3; i++) {
        int h = tid + i*256;
        t[i] = v[i] * inv * nscale[h];
        g_t[(size_t)n*HDIM + h] = __float2bfloat16(t[i]);
    }

    float p[16];
#pragma unroll
    for (int e = 0; e < 16; e++) p[e] = 0.f;
#pragma unroll
    for (int i = 0; i < 3; i++) {
        int h = tid + i*256;
#pragma unroll
        for (int e = 0; e < 16; e++) p[e] += t[i] * gw[e*HDIM + h];
    }
#pragma unroll
    for (int e = 0; e < 16; e++)
#pragma unroll
        for (int o = 16; o; o >>= 1) p[e] += __shfl_xor_sync(0xffffffffu, p[e], o);
    if (lane == 0) {
#pragma unroll
        for (int e = 0; e < 16; e++) sg[warp][e] = p[e];
    }
    __syncthreads();
    if (tid < 16) {
        float s = gb[tid];
#pragma unroll
        for (int w = 0; w < 8; w++) s += sg[w][tid];
        logits[tid] = s;
    }
    __syncthreads();

    if (tid == 0) {
        float vals[TOPK]; int idx[TOPK];
        bool used[16];
#pragma unroll
        for (int e = 0; e < 16; e++) used[e] = false;
        for (int k = 0; k < TOPK; k++) {
            float best = -1e30f; int bi = 0;
            for (int e = 0; e < 16; e++)
                if (!used[e] && logits[e] > best) { best = logits[e]; bi = e; }
            used[bi] = true; vals[k] = best; idx[k] = bi;
        }
        float m = vals[0], s = 0.f, w4[TOPK];
        for (int k = 0; k < TOPK; k++) { w4[k] = expf(vals[k] - m); s += w4[k]; }
        float rs = 1.f / s;
        for (int k = 0; k < TOPK; k++) {
            g_topk_idx[n*TOPK + k] = idx[k];
            g_topk_w[n*TOPK + k]   = w4[k] * rs;
        }
    }
}

// ---------------- kernel 2: fused histogram + scan + scatter (1 CTA) ----------------
__global__ __launch_bounds__(1024) void sortscan_k() {
    __shared__ int scnt[NEXP];
    __shared__ int soff[NEXP];
    __shared__ int scur[NEXP];
    int tid = threadIdx.x;
    if (tid < NEXP) scnt[tid] = 0;
    __syncthreads();
#pragma unroll
    for (int i = 0; i < NSLOT/1024; i++)
        atomicAdd(&scnt[g_topk_idx[tid + i*1024]], 1);
    __syncthreads();
    if (tid == 0) {
        int run = 0;
        for (int e = 0; e < NEXP; e++) {
            soff[e] = run; scur[e] = run; run += scnt[e];
        }
    }
    __syncthreads();
    if (tid < NEXP) { g_cnt[tid] = scnt[tid]; g_off[tid] = soff[tid]; }
#pragma unroll
    for (int i = 0; i < NSLOT/1024; i++) {
        int idx = tid + i*1024;
        int e = g_topk_idx[idx];
        int pos = atomicAdd(&scur[e], 1);
        g_perm[pos] = idx >> 2;      // token
        g_slot[idx] = pos;
    }
}

// ================= GEMM core (R6-proven) =================
// Tile: 128(m) x 128(n), k-stage 64. 256 thr, 2 CTA/SM. warp_m=(w&3)*32, warp_n=(w>>2)*64.

struct FragAcc { float a[2][8][4]; };

__device__ __forceinline__ void gemm_compute_stage(
    uint32_t Ab, uint32_t Bb, int lane, int warp_m, int warp_n, FragAcc& acc)
{
    int g = lane >> 3, r8 = lane & 7;
#pragma unroll
    for (int kk = 0; kk < 4; kk++) {
        int cb = kk * 2;
        uint32_t af[2][4], bf[8][2];
#pragma unroll
        for (int im = 0; im < 2; im++) {
            int row = warp_m + im*16 + (g & 1)*8 + r8;
            int ch  = cb + (g >> 1);
            uint32_t addr = Ab + row*128 + ((ch ^ (row & 7)) * 16);
            LDSM4(af[im][0], af[im][1], af[im][2], af[im][3], addr);
        }
#pragma unroll
        for (int p = 0; p < 4; p++) {
            int row = warp_n + p*16 + (g >> 1)*8 + r8;
            int ch  = cb + (g & 1);
            uint32_t addr = Bb + row*128 + ((ch ^ (row & 7)) * 16);
            LDSM4(bf[2*p][0], bf[2*p][1], bf[2*p+1][0], bf[2*p+1][1], addr);
        }
#pragma unroll
        for (int im = 0; im < 2; im++)
#pragma unroll
            for (int jn = 0; jn < 8; jn++)
                mma_bf16(acc.a[im][jn], af[im], bf[jn]);
    }
}

__device__ __forceinline__ void prefetch_stage(
    uint32_t sb, int s, int kt,
    const __nv_bfloat16* arow, const __nv_bfloat16* brow,
    int lrow, int lc0)
{
    uint32_t Ab = sb + (uint32_t)(s % NBUF) * STGBYTES;
    uint32_t Bb = Ab + 16384;
    int xr = lrow & 7;
#pragma unroll
    for (int c = 0; c < 4; c++) {
        int cc = lc0 + c;
        CPASYNC16(Ab + lrow*128 + ((cc ^ xr) * 16), arow + kt + cc*8);
    }
#pragma unroll
    for (int c = 0; c < 4; c++) {
        int cc = lc0 + c;
        CPASYNC16(Bb + lrow*128 + ((cc ^ xr) * 16), brow + kt + cc*8);
    }
}

// ---------------- kernel 3: grouped GEMM1 + swiglu ----------------
__global__ __launch_bounds__(256, 2) void gemm1_k(const float* __restrict__ b1)
{
    int e  = blockIdx.z;
    int Me = g_cnt[e];
    int m0 = blockIdx.x * 128;
    if (m0 >= Me) return;
    int n0  = blockIdx.y * 128;
    int off = g_off[e];

    extern __shared__ char smem[];
    uint32_t sb = smem_u32(smem);
    int tid = threadIdx.x, warp = tid >> 5, lane = tid & 31;
    int warp_m = (warp & 3) * 32, warp_n = (warp >> 2) * 64;

    int lrow = tid >> 1;
    int lc0  = (tid & 1) * 4;
    int am = m0 + lrow;
    int tok = (am < Me) ? g_perm[off + am] : g_perm[off];
    const __nv_bfloat16* arow = g_t + (size_t)tok * HDIM;
    const __nv_bfloat16* brow = g_w1b + (size_t)e * I2 * HDIM + (size_t)(n0 + lrow) * HDIM;

    FragAcc acc;
#pragma unroll
    for (int a = 0; a < 2; a++)
#pragma unroll
        for (int b = 0; b < 8; b++)
#pragma unroll
            for (int c = 0; c < 4; c++) acc.a[a][b][c] = 0.f;

    const int NS = HDIM / KSTG;  // 12
    prefetch_stage(sb, 0, 0, arow, brow, lrow, lc0); CPCOMMIT();
    prefetch_stage(sb, 1, KSTG, arow, brow, lrow, lc0); CPCOMMIT();

    for (int s = 0; s < NS; s++) {
        CPWAIT1();
        __syncthreads();
        if (s + 2 < NS) prefetch_stage(sb, s + 2, (s + 2) * KSTG, arow, brow, lrow, lc0);
        CPCOMMIT();
        uint32_t Ab = sb + (uint32_t)(s % NBUF) * STGBYTES;
        gemm_compute_stage(Ab, Ab + 16384, lane, warp_m, warp_n, acc);
        __syncthreads();
    }

    // epilogue: bias + swiglu -> bf16 g_a
    const float* B1 = b1 + (size_t)e * I2 + n0;
#pragma unroll
    for (int im = 0; im < 2; im++) {
        int gr = lane >> 2, tg = lane & 3;
        int ml = warp_m + im*16 + gr;
#pragma unroll
        for (int jn = 0; jn < 8; jn++) {
            int nl = warp_n + jn*8 + tg*2;
            float be = B1[nl], bo = B1[nl + 1];
#pragma unroll
            for (int rr = 0; rr < 2; rr++) {
                int r = ml + rr*8;
                if (m0 + r < Me) {
                    float hg = acc.a[im][jn][rr*2+0] + be;
                    float hl = acc.a[im][jn][rr*2+1] + bo;
                    hg = fminf(hg, 7.f);
                    hl = fminf(fmaxf(hl, -7.f), 7.f);
                    float av = hg / (1.f + expf(-1.702f * hg)) * (hl + 1.f);
                    g_a[(size_t)(off + m0 + r)*IDIM + ((n0 + nl) >> 1)] = __float2bfloat16(av);
                }
            }
        }
    }
}

// ---------------- kernel 4: grouped GEMM2 ----------------
__global__ __launch_bounds__(256, 2) void gemm2_k(const float* __restrict__ b2)
{
    int e  = blockIdx.z;
    int Me = g_cnt[e];
    int m0 = blockIdx.x * 128;
    if (m0 >= Me) return;
    int n0  = blockIdx.y * 128;
    int off = g_off[e];

    extern __shared__ char smem[];
    uint32_t sb = smem_u32(smem);
    int tid = threadIdx.x, warp = tid >> 5, lane = tid & 31;
    int warp_m = (warp & 3) * 32, warp_n = (warp >> 2) * 64;

    int lrow = tid >> 1;
    int lc0  = (tid & 1) * 4;
    int arowi = (m0 + lrow < Me) ? (m0 + lrow) : 0;
    const __nv_bfloat16* arow = g_a + (size_t)(off + arowi) * IDIM;
    const __nv_bfloat16* brow = g_w2b + (size_t)e * HDIM * IDIM + (size_t)(n0 + lrow) * IDIM;

    FragAcc acc;
#pragma unroll
    for (int a = 0; a < 2; a++)
#pragma unroll
        for (int b = 0; b < 8; b++)
#pragma unroll
            for (int c = 0; c < 4; c++) acc.a[a][b][c] = 0.f;

    const int NS = IDIM / KSTG;  // 24
    prefetch_stage(sb, 0, 0, arow, brow, lrow, lc0); CPCOMMIT();
    prefetch_stage(sb, 1, KSTG, arow, brow, lrow, lc0); CPCOMMIT();

    for (int s = 0; s < NS; s++) {
        CPWAIT1();
        __syncthreads();
        if (s + 2 < NS) prefetch_stage(sb, s + 2, (s + 2) * KSTG, arow, brow, lrow, lc0);
        CPCOMMIT();
        uint32_t Ab = sb + (uint32_t)(s % NBUF) * STGBYTES;
        gemm_compute_stage(Ab, Ab + 16384, lane, warp_m, warp_n, acc);
        __syncthreads();
    }

    const float* B2 = b2 + (size_t)e * HDIM + n0;
#pragma unroll
    for (int im = 0; im < 2; im++) {
        int gr = lane >> 2, tg = lane & 3;
        int ml = warp_m + im*16 + gr;
#pragma unroll
        for (int jn = 0; jn < 8; jn++) {
            int nl = warp_n + jn*8 + tg*2;
            float be = B2[nl], bo = B2[nl + 1];
#pragma unroll
            for (int rr = 0; rr < 2; rr++) {
                int r = ml + rr*8;
                if (m0 + r < Me) {
                    float2 v = make_float2(acc.a[im][jn][rr*2+0] + be,
                                           acc.a[im][jn][rr*2+1] + bo);
                    *reinterpret_cast<float2*>(
                        g_y + (size_t)(off + m0 + r)*HDIM + n0 + nl) = v;
                }
            }
        }
    }
}

// ---------------- kernel 5: combine ----------------
__global__ __launch_bounds__(256) void combine_k(
    const float* __restrict__ x, float* __restrict__ out)
{
    int n = blockIdx.x, tid = threadIdx.x;
    int s[TOPK]; float w[TOPK];
#pragma unroll
    for (int k = 0; k < TOPK; k++) {
        s[k] = g_slot[n*TOPK + k];
        w[k] = g_topk_w[n*TOPK + k];
    }
#pragma unroll
    for (int i = 0; i < 3; i++) {
        int h = tid + i*256;
        float acc = x[(size_t)n*HDIM + h];
#pragma unroll
        for (int k = 0; k < TOPK; k++)
            acc += w[k] * g_y[(size_t)s[k]*HDIM + h];
        out[(size_t)n*HDIM + h] = acc;
    }
}

// ---------------- launch ----------------
extern "C" void kernel_launch(void* const* d_in, const int* in_sizes, int n_in,
                              void* d_out, int out_size)
{
    const float* x      = (const float*)d_in[0];
    const float* nscale = (const float*)d_in[1];
    const float* gw     = (const float*)d_in[2];
    const float* gb     = (const float*)d_in[3];
    const float* w1     = (const float*)d_in[4];
    const float* b1     = (const float*)d_in[5];
    const float* w2     = (const float*)d_in[6];
    const float* b2     = (const float*)d_in[7];
    float* out = (float*)d_out;

    cudaFuncSetAttribute(gemm1_k, cudaFuncAttributeMaxDynamicSharedMemorySize, SMEM_BYTES);
    cudaFuncSetAttribute(gemm2_k, cudaFuncAttributeMaxDynamicSharedMemorySize, SMEM_BYTES);

    const int nconv = (W1ELEMS/4 + W2ELEMS/4 + 255) / 256;
    convw_k<<<nconv, 256>>>((const float4*)w1, (const float4*)w2);   // launch 0
    router_k<<<N_TOK, 256>>>(x, nscale, gw, gb);                     // launch 1
    sortscan_k<<<1, 1024>>>();                                       // launch 2
    gemm1_k<<<dim3(16, I2/128, NEXP), 256, SMEM_BYTES>>>(b1);        // launch 3 (ncu target)
    gemm2_k<<<dim3(16, HDIM/128, NEXP), 256, SMEM_BYTES>>>(b2);      // launch 4
    combine_k<<<N_TOK, 256>>>(x, out);                               // launch 5
}

// round 9
// speedup vs baseline: 1.6377x; 1.0018x over previous
#include <cuda_runtime.h>
#include <cuda_bf16.h>
#include <cstdint>
#include <math.h>

// Problem constants
#define N_TOK 2048      // B*T
#define HDIM  768
#define NEXP  16
#define TOPK  4
#define I2    3072      // 2*I
#define IDIM  1536      // I
#define NSLOT (N_TOK*TOPK)
#define W1ELEMS (NEXP*I2*HDIM)
#define W2ELEMS (NEXP*HDIM*IDIM)

// GEMM pipeline config
#define KSTG  64                      // k per stage (64 bf16 = 128B rows)
#define NBUF  3
#define STGBYTES 32768                // A 16KB + B 16KB (both bf16)
#define SMEM_BYTES (NBUF*STGBYTES)    // 98304

// ---------------- scratch (static __device__, no allocs) ----------------
__device__ __align__(16) __nv_bfloat16 g_t[N_TOK*HDIM];
__device__ __align__(16) __nv_bfloat16 g_w1b[W1ELEMS];
__device__ __align__(16) __nv_bfloat16 g_w2b[W2ELEMS];
__device__ __align__(16) __nv_bfloat16 g_a[(size_t)NSLOT*IDIM];
__device__ float g_y[(size_t)NSLOT*HDIM];
__device__ int   g_topk_idx[NSLOT];
__device__ float g_topk_w[NSLOT];
__device__ int   g_cnt[NEXP];
__device__ int   g_off[NEXP];
__device__ int   g_perm[NSLOT];
__device__ int   g_slot[NSLOT];

// ---------------- asm helpers ----------------
__device__ __forceinline__ uint32_t smem_u32(const void* p) {
    uint32_t a;
    asm("{ .reg .u64 t; cvta.to.shared.u64 t, %1; cvt.u32.u64 %0, t; }" : "=r"(a) : "l"(p));
    return a;
}
__device__ __forceinline__ uint32_t packbf2(float lo, float hi) {
    __nv_bfloat162 t = __floats2bfloat162_rn(lo, hi);
    return *reinterpret_cast<uint32_t*>(&t);
}
#define CPASYNC16(dst, src) \
    asm volatile("cp.async.cg.shared.global [%0], [%1], 16;" :: "r"(dst), "l"(src) : "memory")
#define CPCOMMIT() asm volatile("cp.async.commit_group;" ::: "memory")
#define CPWAIT1()  asm volatile("cp.async.wait_group 1;" ::: "memory")
#define LDSM4(r0, r1, r2, r3, addr) \
    asm volatile("ldmatrix.sync.aligned.m8n8.x4.shared.b16 {%0,%1,%2,%3}, [%4];" \
        : "=r"(r0), "=r"(r1), "=r"(r2), "=r"(r3) : "r"(addr))

__device__ __forceinline__ void mma_bf16(float* d, const uint32_t* a, const uint32_t* b) {
    asm volatile(
        "mma.sync.aligned.m16n8k16.row.col.f32.bf16.bf16.f32 "
        "{%0,%1,%2,%3},{%4,%5,%6,%7},{%8,%9},{%0,%1,%2,%3};"
        : "+f"(d[0]), "+f"(d[1]), "+f"(d[2]), "+f"(d[3])
        : "r"(a[0]), "r"(a[1]), "r"(a[2]), "r"(a[3]),
          "r"(b[0]), "r"(b[1]));
}

// ---------------- kernel 0: weight fp32 -> bf16 ----------------
__global__ __launch_bounds__(256) void convw_k(
    const float4* __restrict__ w1, const float4* __restrict__ w2)
{
    int i = blockIdx.x * blockDim.x + threadIdx.x;
    const int n1 = W1ELEMS / 4, n2 = W2ELEMS / 4;
    if (i < n1) {
        float4 v = w1[i];
        reinterpret_cast<uint2*>(g_w1b)[i] = make_uint2(packbf2(v.x, v.y), packbf2(v.z, v.w));
    } else {
        i -= n1;
        if (i < n2) {
            float4 v = w2[i];
            reinterpret_cast<uint2*>(g_w2b)[i] = make_uint2(packbf2(v.x, v.y), packbf2(v.z, v.w));
        }
    }
}

// ---------------- kernel 1: router (no count atomics) ----------------
__global__ __launch_bounds__(256) void router_k(
    const float* __restrict__ x, const float* __restrict__ nscale,
    const float* __restrict__ gw, const float* __restrict__ gb)
{
    int n = blockIdx.x;
    int tid = threadIdx.x, warp = tid >> 5, lane = tid & 31;
    const float* xp = x + (size_t)n * HDIM;

    float v[3];
    float ss = 0.f;
#pragma unroll
    for (int i = 0; i < 3; i++) { v[i] = xp[tid + i*256]; ss += v[i]*v[i]; }
#pragma unroll
    for (int o = 16; o; o >>= 1) ss += __shfl_xor_sync(0xffffffffu, ss, o);

    __shared__ float sred[8];
    __shared__ float sg[8][16];
    __shared__ float logits[16];
    if (lane == 0) sred[warp] = ss;
    __syncthreads();
    float tot = 0.f;
#pragma unroll
    for (int w = 0; w < 8; w++) tot += sred[w];
    float inv = rsqrtf(tot * (1.0f/HDIM) + 1e-5f);

    float t[3];
#pragma unroll
    for (int i = 0; i < 3; i++) {
        int h = tid + i*256;
        t[i] = v[i] * inv * nscale[h];
        g_t[(size_t)n*HDIM + h] = __float2bfloat16(t[i]);
    }

    float p[16];
#pragma unroll
    for (int e = 0; e < 16; e++) p[e] = 0.f;
#pragma unroll
    for (int i = 0; i < 3; i++) {
        int h = tid + i*256;
#pragma unroll
        for (int e = 0; e < 16; e++) p[e] += t[i] * gw[e*HDIM + h];
    }
#pragma unroll
    for (int e = 0; e < 16; e++)
#pragma unroll
        for (int o = 16; o; o >>= 1) p[e] += __shfl_xor_sync(0xffffffffu, p[e], o);
    if (lane == 0) {
#pragma unroll
        for (int e = 0; e < 16; e++) sg[warp][e] = p[e];
    }
    __syncthreads();
    if (tid < 16) {
        float s = gb[tid];
#pragma unroll
        for (int w = 0; w < 8; w++) s += sg[w][tid];
        logits[tid] = s;
    }
    __syncthreads();

    if (tid == 0) {
        float vals[TOPK]; int idx[TOPK];
        bool used[16];
#pragma unroll
        for (int e = 0; e < 16; e++) used[e] = false;
        for (int k = 0; k < TOPK; k++) {
            float best = -1e30f; int bi = 0;
            for (int e = 0; e < 16; e++)
                if (!used[e] && logits[e] > best) { best = logits[e]; bi = e; }
            used[bi] = true; vals[k] = best; idx[k] = bi;
        }
        float m = vals[0], s = 0.f, w4[TOPK];
        for (int k = 0; k < TOPK; k++) { w4[k] = expf(vals[k] - m); s += w4[k]; }
        float rs = 1.f / s;
        for (int k = 0; k < TOPK; k++) {
            g_topk_idx[n*TOPK + k] = idx[k];
            g_topk_w[n*TOPK + k]   = w4[k] * rs;
        }
    }
}

// ---------------- kernel 2: fused histogram + scan + scatter (1 CTA) ----------------
__global__ __launch_bounds__(1024) void sortscan_k() {
    __shared__ int scnt[NEXP];
    __shared__ int soff[NEXP];
    __shared__ int scur[NEXP];
    int tid = threadIdx.x;
    if (tid < NEXP) scnt[tid] = 0;
    __syncthreads();
#pragma unroll
    for (int i = 0; i < NSLOT/1024; i++)
        atomicAdd(&scnt[g_topk_idx[tid + i*1024]], 1);
    __syncthreads();
    if (tid == 0) {
        int run = 0;
        for (int e = 0; e < NEXP; e++) {
            soff[e] = run; scur[e] = run; run += scnt[e];
        }
    }
    __syncthreads();
    if (tid < NEXP) { g_cnt[tid] = scnt[tid]; g_off[tid] = soff[tid]; }
#pragma unroll
    for (int i = 0; i < NSLOT/1024; i++) {
        int idx = tid + i*1024;
        int e = g_topk_idx[idx];
        int pos = atomicAdd(&scur[e], 1);
        g_perm[pos] = idx >> 2;      // token
        g_slot[idx] = pos;
    }
}

// ================= GEMM core =================
// Tile: 128(m) x 128(n), k-stage 64. 256 thr, 2 CTA/SM. warp_m=(w&3)*32, warp_n=(w>>2)*64.
// Single-sync 3-buffer cp.async pipeline.

struct FragAcc { float a[2][8][4]; };

__device__ __forceinline__ void gemm_compute_stage(
    uint32_t Ab, uint32_t Bb, int lane, int warp_m, int warp_n, FragAcc& acc)
{
    int g = lane >> 3, r8 = lane & 7;
#pragma unroll
    for (int kk = 0; kk < 4; kk++) {
        int cb = kk * 2;
        uint32_t af[2][4], bf[8][2];
#pragma unroll
        for (int im = 0; im < 2; im++) {
            int row = warp_m + im*16 + (g & 1)*8 + r8;
            int ch  = cb + (g >> 1);
            uint32_t addr = Ab + row*128 + ((ch ^ (row & 7)) * 16);
            LDSM4(af[im][0], af[im][1], af[im][2], af[im][3], addr);
        }
#pragma unroll
        for (int p = 0; p < 4; p++) {
            int row = warp_n + p*16 + (g >> 1)*8 + r8;
            int ch  = cb + (g & 1);
            uint32_t addr = Bb + row*128 + ((ch ^ (row & 7)) * 16);
            LDSM4(bf[2*p][0], bf[2*p][1], bf[2*p+1][0], bf[2*p+1][1], addr);
        }
#pragma unroll
        for (int im = 0; im < 2; im++)
#pragma unroll
            for (int jn = 0; jn < 8; jn++)
                mma_bf16(acc.a[im][jn], af[im], bf[jn]);
    }
}

__device__ __forceinline__ void prefetch_stage(
    uint32_t sb, int s, int kt,
    const __nv_bfloat16* arow, const __nv_bfloat16* brow,
    int lrow, int lc0)
{
    uint32_t Ab = sb + (uint32_t)(s % NBUF) * STGBYTES;
    uint32_t Bb = Ab + 16384;
    int xr = lrow & 7;
#pragma unroll
    for (int c = 0; c < 4; c++) {
        int cc = lc0 + c;
        CPASYNC16(Ab + lrow*128 + ((cc ^ xr) * 16), arow + kt + cc*8);
    }
#pragma unroll
    for (int c = 0; c < 4; c++) {
        int cc = lc0 + c;
        CPASYNC16(Bb + lrow*128 + ((cc ^ xr) * 16), brow + kt + cc*8);
    }
}

// ---------------- kernel 3: grouped GEMM1 + swiglu ----------------
__global__ __launch_bounds__(256, 2) void gemm1_k(const float* __restrict__ b1)
{
    int e  = blockIdx.z;
    int Me = g_cnt[e];
    int m0 = blockIdx.x * 128;
    if (m0 >= Me) return;
    int n0  = blockIdx.y * 128;
    int off = g_off[e];

    extern __shared__ char smem[];
    uint32_t sb = smem_u32(smem);
    int tid = threadIdx.x, warp = tid >> 5, lane = tid & 31;
    int warp_m = (warp & 3) * 32, warp_n = (warp >> 2) * 64;

    int lrow = tid >> 1;
    int lc0  = (tid & 1) * 4;
    int am = m0 + lrow;
    int tok = (am < Me) ? g_perm[off + am] : g_perm[off];
    const __nv_bfloat16* arow = g_t + (size_t)tok * HDIM;
    const __nv_bfloat16* brow = g_w1b + (size_t)e * I2 * HDIM + (size_t)(n0 + lrow) * HDIM;

    FragAcc acc;
#pragma unroll
    for (int a = 0; a < 2; a++)
#pragma unroll
        for (int b = 0; b < 8; b++)
#pragma unroll
            for (int c = 0; c < 4; c++) acc.a[a][b][c] = 0.f;

    const int NS = HDIM / KSTG;  // 12
    prefetch_stage(sb, 0, 0, arow, brow, lrow, lc0); CPCOMMIT();
    prefetch_stage(sb, 1, KSTG, arow, brow, lrow, lc0); CPCOMMIT();

    for (int s = 0; s < NS; s++) {
        CPWAIT1();
        __syncthreads();   // stage s data visible; all warps done with stage s-1 compute
        if (s + 2 < NS) prefetch_stage(sb, s + 2, (s + 2) * KSTG, arow, brow, lrow, lc0);
        CPCOMMIT();
        uint32_t Ab = sb + (uint32_t)(s % NBUF) * STGBYTES;
        gemm_compute_stage(Ab, Ab + 16384, lane, warp_m, warp_n, acc);
    }

    // epilogue: bias + swiglu -> bf16 g_a
    const float* B1 = b1 + (size_t)e * I2 + n0;
#pragma unroll
    for (int im = 0; im < 2; im++) {
        int gr = lane >> 2, tg = lane & 3;
        int ml = warp_m + im*16 + gr;
#pragma unroll
        for (int jn = 0; jn < 8; jn++) {
            int nl = warp_n + jn*8 + tg*2;
            float be = B1[nl], bo = B1[nl + 1];
#pragma unroll
            for (int rr = 0; rr < 2; rr++) {
                int r = ml + rr*8;
                if (m0 + r < Me) {
                    float hg = acc.a[im][jn][rr*2+0] + be;
                    float hl = acc.a[im][jn][rr*2+1] + bo;
                    hg = fminf(hg, 7.f);
                    hl = fminf(fmaxf(hl, -7.f), 7.f);
                    float av = hg / (1.f + expf(-1.702f * hg)) * (hl + 1.f);
                    g_a[(size_t)(off + m0 + r)*IDIM + ((n0 + nl) >> 1)] = __float2bfloat16(av);
                }
            }
        }
    }
}

// ---------------- kernel 4: grouped GEMM2 ----------------
__global__ __launch_bounds__(256, 2) void gemm2_k(const float* __restrict__ b2)
{
    int e  = blockIdx.z;
    int Me = g_cnt[e];
    int m0 = blockIdx.x * 128;
    if (m0 >= Me) return;
    int n0  = blockIdx.y * 128;
    int off = g_off[e];

    extern __shared__ char smem[];
    uint32_t sb = smem_u32(smem);
    int tid = threadIdx.x, warp = tid >> 5, lane = tid & 31;
    int warp_m = (warp & 3) * 32, warp_n = (warp >> 2) * 64;

    int lrow = tid >> 1;
    int lc0  = (tid & 1) * 4;
    int arowi = (m0 + lrow < Me) ? (m0 + lrow) : 0;
    const __nv_bfloat16* arow = g_a + (size_t)(off + arowi) * IDIM;
    const __nv_bfloat16* brow = g_w2b + (size_t)e * HDIM * IDIM + (size_t)(n0 + lrow) * IDIM;

    FragAcc acc;
#pragma unroll
    for (int a = 0; a < 2; a++)
#pragma unroll
        for (int b = 0; b < 8; b++)
#pragma unroll
            for (int c = 0; c < 4; c++) acc.a[a][b][c] = 0.f;

    const int NS = IDIM / KSTG;  // 24
    prefetch_stage(sb, 0, 0, arow, brow, lrow, lc0); CPCOMMIT();
    prefetch_stage(sb, 1, KSTG, arow, brow, lrow, lc0); CPCOMMIT();

    for (int s = 0; s < NS; s++) {
        CPWAIT1();
        __syncthreads();
        if (s + 2 < NS) prefetch_stage(sb, s + 2, (s + 2) * KSTG, arow, brow, lrow, lc0);
        CPCOMMIT();
        uint32_t Ab = sb + (uint32_t)(s % NBUF) * STGBYTES;
        gemm_compute_stage(Ab, Ab + 16384, lane, warp_m, warp_n, acc);
    }

    const float* B2 = b2 + (size_t)e * HDIM + n0;
#pragma unroll
    for (int im = 0; im < 2; im++) {
        int gr = lane >> 2, tg = lane & 3;
        int ml = warp_m + im*16 + gr;
#pragma unroll
        for (int jn = 0; jn < 8; jn++) {
            int nl = warp_n + jn*8 + tg*2;
            float be = B2[nl], bo = B2[nl + 1];
#pragma unroll
            for (int rr = 0; rr < 2; rr++) {
                int r = ml + rr*8;
                if (m0 + r < Me) {
                    float2 v = make_float2(acc.a[im][jn][rr*2+0] + be,
                                           acc.a[im][jn][rr*2+1] + bo);
                    *reinterpret_cast<float2*>(
                        g_y + (size_t)(off + m0 + r)*HDIM + n0 + nl) = v;
                }
            }
        }
    }
}

// ---------------- kernel 5: combine ----------------
__global__ __launch_bounds__(256) void combine_k(
    const float* __restrict__ x, float* __restrict__ out)
{
    int n = blockIdx.x, tid = threadIdx.x;
    int s[TOPK]; float w[TOPK];
#pragma unroll
    for (int k = 0; k < TOPK; k++) {
        s[k] = g_slot[n*TOPK + k];
        w[k] = g_topk_w[n*TOPK + k];
    }
#pragma unroll
    for (int i = 0; i < 3; i++) {
        int h = tid + i*256;
        float acc = x[(size_t)n*HDIM + h];
#pragma unroll
        for (int k = 0; k < TOPK; k++)
            acc += w[k] * g_y[(size_t)s[k]*HDIM + h];
        out[(size_t)n*HDIM + h] = acc;
    }
}

// ---------------- launch ----------------
extern "C" void kernel_launch(void* const* d_in, const int* in_sizes, int n_in,
                              void* d_out, int out_size)
{
    const float* x      = (const float*)d_in[0];
    const float* nscale = (const float*)d_in[1];
    const float* gw     = (const float*)d_in[2];
    const float* gb     = (const float*)d_in[3];
    const float* w1     = (const float*)d_in[4];
    const float* b1     = (const float*)d_in[5];
    const float* w2     = (const float*)d_in[6];
    const float* b2     = (const float*)d_in[7];
    float* out = (float*)d_out;

    cudaFuncSetAttribute(gemm1_k, cudaFuncAttributeMaxDynamicSharedMemorySize, SMEM_BYTES);
    cudaFuncSetAttribute(gemm2_k, cudaFuncAttributeMaxDynamicSharedMemorySize, SMEM_BYTES);

    const int nconv = (W1ELEMS/4 + W2ELEMS/4 + 255) / 256;
    convw_k<<<nconv, 256>>>((const float4*)w1, (const float4*)w2);   // launch 0
    router_k<<<N_TOK, 256>>>(x, nscale, gw, gb);                     // launch 1
    sortscan_k<<<1, 1024>>>();                                       // launch 2
    gemm1_k<<<dim3(16, I2/128, NEXP), 256, SMEM_BYTES>>>(b1);        // launch 3 (ncu target)
    gemm2_k<<<dim3(16, HDIM/128, NEXP), 256, SMEM_BYTES>>>(b2);      // launch 4
    combine_k<<<N_TOK, 256>>>(x, out);                               // launch 5
}